// round 3
// baseline (speedup 1.0000x reference)
#include <cuda_runtime.h>

#define NCLS   64
#define DIM    256
#define NROWS  65536
#define MTILE  256          // rows per block in main kernel
#define MAIN_THREADS 512    // 16 warps, each owns one m16 slice
#define MAIN_BLOCKS  512    // 131072 / 256
#define WPITCH 260          // padded W row pitch (floats) -> conflict-free B loads
#define FPITCH 36           // padded feat-chunk row pitch  -> conflict-free A loads

// ---------------- device scratch (no allocations allowed) ----------------
__device__ float  g_sum[2][NCLS][DIM];   // raw segment sums (src, trg)
__device__ float  g_cnt[2][NCLS];
__device__ double g_acc;
__device__ int    g_lstride;             // 1 = labels int32, 2 = labels int64

// ---------------- helpers ----------------
__device__ __forceinline__ unsigned f2tf32(float x) {
    unsigned r;
    asm("cvt.rna.tf32.f32 %0, %1;" : "=r"(r) : "f"(x));
    return r;
}

__device__ __forceinline__ void mma_tf32(float (&d)[4], const unsigned (&a)[4], const unsigned (&b)[2]) {
    asm volatile(
        "mma.sync.aligned.m16n8k8.row.col.f32.tf32.tf32.f32 "
        "{%0,%1,%2,%3}, {%4,%5,%6,%7}, {%8,%9}, {%0,%1,%2,%3};\n"
        : "+f"(d[0]), "+f"(d[1]), "+f"(d[2]), "+f"(d[3])
        : "r"(a[0]), "r"(a[1]), "r"(a[2]), "r"(a[3]),
          "r"(b[0]), "r"(b[1]));
}

__device__ __forceinline__ float qmax(float v) {
    v = fmaxf(v, __shfl_xor_sync(0xffffffffu, v, 1));
    v = fmaxf(v, __shfl_xor_sync(0xffffffffu, v, 2));
    return v;
}
__device__ __forceinline__ float qsum(float v) {
    v += __shfl_xor_sync(0xffffffffu, v, 1);
    v += __shfl_xor_sync(0xffffffffu, v, 2);
    return v;
}

// ---------------- kernel -1: detect label dtype (int32 vs int64) ----------
// Safe: reads only the first 512 bytes of a >=256KB buffer. If labels are
// int64 (values 0..63), every odd 32-bit word is 0. For genuine int32 labels
// the odds of 64 consecutive odd words all being 0 are (1/64)^64 ~ 0.
__global__ void k_detect(const int* __restrict__ lbl) {
    bool odd_zero = true;
    #pragma unroll
    for (int i = 0; i < 64; ++i) odd_zero &= (lbl[2 * i + 1] == 0);
    g_lstride = odd_zero ? 2 : 1;
}

// ---------------- kernel 0: zero scratch ----------------
__global__ void k_zero() {
    int idx = blockIdx.x * blockDim.x + threadIdx.x;   // 64*512 = 32768
    float* s = &g_sum[0][0][0];
    if (idx < 2 * NCLS * DIM) s[idx] = 0.f;
    if (idx < 2 * NCLS) (&g_cnt[0][0])[idx] = 0.f;
    if (idx == 0) g_acc = 0.0;
}

// ---------------- kernel 1: segment sums via smem bins ----------------
// grid 256 blocks (256 rows each), 256 threads (one per column), dyn smem 64KB
__global__ void k_segsum(const float* __restrict__ feat,
                         const int* __restrict__ lbl32, int which) {
    extern __shared__ float bins[];            // [64][256]
    __shared__ int cbin[NCLS];
    const int ls = g_lstride;
    int d = threadIdx.x;
    #pragma unroll
    for (int c = 0; c < NCLS; ++c) bins[c * DIM + d] = 0.f;
    if (d < NCLS) cbin[d] = 0;
    __syncthreads();

    int base = blockIdx.x * 256;
    for (int r = 0; r < 256; r += 4) {
        int c0 = lbl32[(base + r + 0) * ls] & 63;
        int c1 = lbl32[(base + r + 1) * ls] & 63;
        int c2 = lbl32[(base + r + 2) * ls] & 63;
        int c3 = lbl32[(base + r + 3) * ls] & 63;
        float f0 = feat[(size_t)(base + r + 0) * DIM + d];
        float f1 = feat[(size_t)(base + r + 1) * DIM + d];
        float f2 = feat[(size_t)(base + r + 2) * DIM + d];
        float f3 = feat[(size_t)(base + r + 3) * DIM + d];
        bins[c0 * DIM + d] += f0;
        bins[c1 * DIM + d] += f1;
        bins[c2 * DIM + d] += f2;
        bins[c3 * DIM + d] += f3;
        if (d == 0) { cbin[c0]++; cbin[c1]++; cbin[c2]++; cbin[c3]++; }
    }
    __syncthreads();
    #pragma unroll
    for (int c = 0; c < NCLS; ++c)
        atomicAdd(&g_sum[which][c][d], bins[c * DIM + d]);
    if (d < NCLS) atomicAdd(&g_cnt[which][d], (float)cbin[d]);
}

// ---------------- kernel 2: fused tf32 GEMM + softmax/KL ----------------
// Each block: 256 rows x 128 logit cols (cols 0..63 = S, 64..127 = T).
// 16 warps, each owns m16 x n128. Accum in registers, KL epilogue in-place.
#define SMEM_MAIN ((128 * WPITCH + MTILE * FPITCH) * 4 + 3 * NCLS * 4 + 16 * 4)

__global__ void __launch_bounds__(MAIN_THREADS, 1)
k_main(const float* __restrict__ src, const float* __restrict__ trg) {
    extern __shared__ unsigned char smem_raw[];
    unsigned* Ws  = (unsigned*)smem_raw;             // [128][WPITCH] tf32
    unsigned* Fs  = Ws + 128 * WPITCH;               // [256][FPITCH] tf32 (k-chunk)
    float*    inv = (float*)(Fs + MTILE * FPITCH);   // [3][64]
    float*    red = inv + 3 * NCLS;                  // [16]

    const int tid  = threadIdx.x;
    const int w    = tid >> 5;
    const int lane = tid & 31;
    const int g    = lane >> 2;
    const int t    = lane & 3;

    // stage W = [sum_s ; sum_t], converted to tf32
    for (int idx = tid; idx < 128 * DIM; idx += MAIN_THREADS) {
        int c = idx >> 8, k = idx & 255;
        float v = (c < NCLS) ? g_sum[0][c][k] : g_sum[1][c - NCLS][k];
        Ws[c * WPITCH + k] = f2tf32(v);
    }
    if (tid < NCLS) {
        float cs = g_cnt[0][tid], ct = g_cnt[1][tid];
        inv[tid]            = 1.f / cs;
        inv[NCLS + tid]     = 1.f / ct;
        inv[2 * NCLS + tid] = 1.f / (cs + ct);
    }

    // row tile for this block
    const float* fb = (blockIdx.x < 256) ? src : trg;
    const float4* gf = (const float4*)(fb + (size_t)(blockIdx.x & 255) * MTILE * DIM);

    float acc[16][4];
    #pragma unroll
    for (int n = 0; n < 16; ++n)
        #pragma unroll
        for (int j = 0; j < 4; ++j) acc[n][j] = 0.f;

    const int w16 = w * 16;

    for (int kc = 0; kc < 8; ++kc) {       // K chunks of 32
        __syncthreads();                    // protect Fs (and Ws/inv on first iter)
        #pragma unroll
        for (int i = 0; i < 4; ++i) {
            int f4 = tid + i * MAIN_THREADS;      // 0..2047
            int r  = f4 >> 3, q = f4 & 7;
            float4 v = gf[(size_t)r * 64 + kc * 8 + q];
            unsigned* dst = &Fs[r * FPITCH + q * 4];
            dst[0] = f2tf32(v.x); dst[1] = f2tf32(v.y);
            dst[2] = f2tf32(v.z); dst[3] = f2tf32(v.w);
        }
        __syncthreads();

        #pragma unroll
        for (int ks = 0; ks < 4; ++ks) {    // 4 x k8 steps per chunk
            int kk = ks * 8;
            unsigned a[4];
            a[0] = Fs[(w16 + g) * FPITCH + kk + t];
            a[1] = Fs[(w16 + g + 8) * FPITCH + kk + t];
            a[2] = Fs[(w16 + g) * FPITCH + kk + t + 4];
            a[3] = Fs[(w16 + g + 8) * FPITCH + kk + t + 4];
            int kglob = kc * 32 + kk;
            #pragma unroll
            for (int n = 0; n < 16; ++n) {
                unsigned b[2];
                b[0] = Ws[(n * 8 + g) * WPITCH + kglob + t];
                b[1] = Ws[(n * 8 + g) * WPITCH + kglob + t + 4];
                mma_tf32(acc[n], a, b);
            }
        }
    }

    // ---- fused epilogue: per-row 3 softmaxes + symmetrized KLs ----
    // lane owns classes c = 8n + 2t + j (n=0..7, j=0..1): S=acc[n][..], T=acc[n+8][..]
    float Jtot = 0.f;
    #pragma unroll
    for (int half = 0; half < 2; ++half) {  // rows (g) and (g+8)
        int j0 = half * 2;
        float mS = -1e30f, mT = -1e30f, mM = -1e30f;
        #pragma unroll
        for (int i = 0; i < 16; ++i) {
            int n = i >> 1, j = i & 1, c = n * 8 + 2 * t + j;
            float S = acc[n][j0 + j], T = acc[n + 8][j0 + j];
            float ps = S * inv[c];
            float pt = T * inv[NCLS + c];
            float pm = (S + T) * inv[2 * NCLS + c];
            mS = fmaxf(mS, ps); mT = fmaxf(mT, pt); mM = fmaxf(mM, pm);
        }
        mS = qmax(mS); mT = qmax(mT); mM = qmax(mM);

        float zS = 0.f, zT = 0.f, zM = 0.f;
        #pragma unroll
        for (int i = 0; i < 16; ++i) {
            int n = i >> 1, j = i & 1, c = n * 8 + 2 * t + j;
            float S = acc[n][j0 + j], T = acc[n + 8][j0 + j];
            float ps = S * inv[c];
            float pt = T * inv[NCLS + c];
            float pm = (S + T) * inv[2 * NCLS + c];
            zS += __expf(ps - mS); zT += __expf(pt - mT); zM += __expf(pm - mM);
        }
        zS = qsum(zS); zT = qsum(zT); zM = qsum(zM);
        float lseS = mS + __logf(zS);
        float lseT = mT + __logf(zT);
        float lseM = mM + __logf(zM);

        float J = 0.f;
        #pragma unroll
        for (int i = 0; i < 16; ++i) {
            int n = i >> 1, j = i & 1, c = n * 8 + 2 * t + j;
            float S = acc[n][j0 + j], T = acc[n + 8][j0 + j];
            float ls = S * inv[c] - lseS;
            float lt = T * inv[NCLS + c] - lseT;
            float lm = (S + T) * inv[2 * NCLS + c] - lseM;
            float es = __expf(ls), et = __expf(lt), em = __expf(lm);
            J += (et - es) * (lt - ls) + (em - es) * (lm - ls) + (em - et) * (lm - lt);
        }
        Jtot += qsum(J);   // replicated within quad
    }
    // sum across the 8 quads (quads already internally replicated)
    Jtot += __shfl_xor_sync(0xffffffffu, Jtot, 4);
    Jtot += __shfl_xor_sync(0xffffffffu, Jtot, 8);
    Jtot += __shfl_xor_sync(0xffffffffu, Jtot, 16);
    if (lane == 0) red[w] = Jtot;
    __syncthreads();
    if (tid == 0) {
        float bs = 0.f;
        #pragma unroll
        for (int i = 0; i < 16; ++i) bs += red[i];
        atomicAdd(&g_acc, (double)bs);
    }
}

// ---------------- kernel 3: finalize ----------------
__global__ void k_final(float* out) {
    // J terms above omit the 0.5 pair factor: scale = 0.5 / (3 * 2N * C)
    out[0] = (float)(g_acc * (0.5 / (3.0 * 131072.0 * 64.0)));
}

// ---------------- launch ----------------
extern "C" void kernel_launch(void* const* d_in, const int* in_sizes, int n_in,
                              void* d_out, int out_size) {
    const float* src = (const float*)d_in[0];
    const float* trg = (const float*)d_in[1];
    const int*   sl  = (const int*)d_in[2];
    const int*   tl  = (const int*)d_in[3];

    cudaFuncSetAttribute(k_segsum, cudaFuncAttributeMaxDynamicSharedMemorySize, 65536);
    cudaFuncSetAttribute(k_main,   cudaFuncAttributeMaxDynamicSharedMemorySize, SMEM_MAIN);

    k_detect<<<1, 1>>>(sl);
    k_zero<<<64, 512>>>();
    k_segsum<<<256, 256, 65536>>>(src, sl, 0);
    k_segsum<<<256, 256, 65536>>>(trg, tl, 1);
    k_main<<<MAIN_BLOCKS, MAIN_THREADS, SMEM_MAIN>>>(src, trg);
    k_final<<<1, 1>>>((float*)d_out);
}

// round 4
// speedup vs baseline: 1.3467x; 1.3467x over previous
#include <cuda_runtime.h>
#include <cuda_bf16.h>
#include <cstdint>

#define NCLS 64
#define DIM 256
#define NROWS 65536
#define TOTROWS 131072

__device__ __align__(16) __nv_bfloat16 g_featbf[(size_t)TOTROWS * DIM];
__device__ float  g_scratch[512][NCLS * DIM];     // per-block partial bins (32MB)
__device__ float  g_cnt[2][NCLS];
__device__ __align__(16) __nv_bfloat16 g_wbf[4 * 8192];  // W bf16 pre-swizzled, 4 k-chunks
__device__ float  g_inv[3 * NCLS];
__device__ double g_acc;
__device__ int    g_lstride;

__device__ __forceinline__ uint32_t smem_u32(const void* p) {
    uint32_t r;
    asm("{ .reg .u64 t; cvta.to.shared.u64 t, %1; cvt.u32.u64 %0, t; }" : "=r"(r) : "l"(p));
    return r;
}
__device__ __forceinline__ void cpa16(uint32_t dst, const void* src) {
    asm volatile("cp.async.cg.shared.global [%0], [%1], 16;" :: "r"(dst), "l"(src));
}
__device__ __forceinline__ void cp_commit() { asm volatile("cp.async.commit_group;"); }
template<int N> __device__ __forceinline__ void cp_wait() {
    asm volatile("cp.async.wait_group %0;" :: "n"(N));
}
__device__ __forceinline__ uint32_t lds_u32(uint32_t a) {
    uint32_t v; asm volatile("ld.shared.b32 %0, [%1];" : "=r"(v) : "r"(a)); return v;
}
__device__ __forceinline__ void mma_bf16(float* d, const uint32_t* a, const uint32_t* b) {
    asm volatile("mma.sync.aligned.m16n8k16.row.col.f32.bf16.bf16.f32 "
        "{%0,%1,%2,%3}, {%4,%5,%6,%7}, {%8,%9}, {%0,%1,%2,%3};"
        : "+f"(d[0]), "+f"(d[1]), "+f"(d[2]), "+f"(d[3])
        : "r"(a[0]), "r"(a[1]), "r"(a[2]), "r"(a[3]), "r"(b[0]), "r"(b[1]));
}
__device__ __forceinline__ float qmax(float v) {
    v = fmaxf(v, __shfl_xor_sync(~0u, v, 1));
    v = fmaxf(v, __shfl_xor_sync(~0u, v, 2));
    return v;
}
__device__ __forceinline__ float qsum(float v) {
    v += __shfl_xor_sync(~0u, v, 1);
    v += __shfl_xor_sync(~0u, v, 2);
    return v;
}

__global__ void k_detect(const int* __restrict__ lbl) {
    bool oz = true;
    #pragma unroll
    for (int i = 0; i < 64; ++i) oz &= (lbl[2 * i + 1] == 0);
    g_lstride = oz ? 2 : 1;
}

__global__ void k_zero() {
    int i = threadIdx.x;
    if (i < 128) ((float*)g_cnt)[i] = 0.f;
    if (i == 128) g_acc = 0.0;
}

// 512 blocks = 2 feats x 256 chunks x 256 rows; 256 threads (one per column)
__global__ void __launch_bounds__(256) k_segsum(const float* __restrict__ src,
        const float* __restrict__ trg, const int* __restrict__ sl,
        const int* __restrict__ tl) {
    extern __shared__ float bins[];            // [64][256]
    __shared__ int cbin[NCLS];
    const int feat = blockIdx.x >> 8, chunk = blockIdx.x & 255;
    const float* fp = feat ? trg : src;
    const int*   lp = feat ? tl : sl;
    const int ls = g_lstride, d = threadIdx.x;
    #pragma unroll
    for (int c = 0; c < NCLS; ++c) bins[c * DIM + d] = 0.f;
    if (d < NCLS) cbin[d] = 0;
    __syncthreads();

    const int base = chunk * 256;
    const float* fin = fp + (size_t)base * DIM + d;
    __nv_bfloat16* outb = g_featbf + (size_t)(feat * NROWS + base) * DIM + d;

    for (int r0 = 0; r0 < 256; r0 += 8) {
        int cc[8]; float ff[8];
        #pragma unroll
        for (int i = 0; i < 8; ++i) cc[i] = lp[(base + r0 + i) * ls] & 63;
        #pragma unroll
        for (int i = 0; i < 8; ++i) ff[i] = fin[(size_t)(r0 + i) * DIM];
        #pragma unroll
        for (int i = 0; i < 8; ++i) outb[(size_t)(r0 + i) * DIM] = __float2bfloat16(ff[i]);
        #pragma unroll
        for (int i = 0; i < 8; ++i) bins[cc[i] * DIM + d] += ff[i];
        if (d == 0) {
            #pragma unroll
            for (int i = 0; i < 8; ++i) cbin[cc[i]]++;
        }
    }
    __syncthreads();
    #pragma unroll 4
    for (int c = 0; c < NCLS; ++c)
        g_scratch[blockIdx.x][c * DIM + d] = bins[c * DIM + d];
    if (d < NCLS) atomicAdd(&g_cnt[feat][d], (float)cbin[d]);
}

// reduce partials -> W bf16 (swizzled) + inv. 64 blocks x 512 threads
__global__ void k_red() {
    int idx = blockIdx.x * 512 + threadIdx.x;      // 0..32767
    int cls = idx >> 8, k = idx & 255;
    int feat = cls >> 6, c = cls & 63;
    const float* p = &g_scratch[feat * 256][0] + c * DIM + k;
    float s = 0.f;
    #pragma unroll 8
    for (int b = 0; b < 256; ++b) s += p[(size_t)b * (NCLS * DIM)];
    int kc = k >> 6, u = (k >> 3) & 7, e = k & 7;
    int phys = cls * 8 + (u ^ (cls & 7));
    g_wbf[kc * 8192 + phys * 8 + e] = __float2bfloat16(s);
    if (idx < 3 * NCLS) {
        int which = idx >> 6, c2 = idx & 63;
        float cs = g_cnt[0][c2], ct = g_cnt[1][c2];
        g_inv[idx] = (which == 0) ? 1.f / cs : (which == 1) ? 1.f / ct : 1.f / (cs + ct);
    }
}

// fused bf16 GEMM + softmax/KL. 512 blocks x 256 thr (8 warps), 256 rows x 128 cls
#define FS_OFF 65536
#define FS_SZ  32768
#define INV_OFF (FS_OFF + 2 * FS_SZ)
#define RED_OFF (INV_OFF + 768)
#define SMEM_MAIN (RED_OFF + 64)

__global__ void __launch_bounds__(256, 1) k_main() {
    extern __shared__ unsigned char sm[];
    float* inv_s = (float*)(sm + INV_OFF);
    float* red   = (float*)(sm + RED_OFF);
    const uint32_t sb = smem_u32(sm);
    const int tid = threadIdx.x, w = tid >> 5, lane = tid & 31;
    const int g = lane >> 2, t = lane & 3;

    #pragma unroll
    for (int j = 0; j < 16; ++j) {                 // W: 4096 16B units (bf16, pre-swizzled)
        int uu = j * 256 + tid;
        cpa16(sb + uu * 16, g_wbf + uu * 8);
    }
    if (tid < 192) inv_s[tid] = g_inv[tid];

    const __nv_bfloat16* frow = g_featbf + (size_t)blockIdx.x * 256 * DIM;
    #pragma unroll
    for (int j = 0; j < 8; ++j) {                  // F chunk 0
        int uu = j * 256 + tid, row = uu >> 3, u = uu & 7;
        cpa16(sb + FS_OFF + (uint32_t)(row * 8 + (u ^ (row & 7))) * 16,
              frow + (size_t)row * DIM + u * 8);
    }
    cp_commit();

    float acc[2][16][4];
    #pragma unroll
    for (int x = 0; x < 2; ++x)
        #pragma unroll
        for (int y = 0; y < 16; ++y)
            #pragma unroll
            for (int z = 0; z < 4; ++z) acc[x][y][z] = 0.f;

    #pragma unroll
    for (int kc = 0; kc < 4; ++kc) {
        if (kc < 3) {
            #pragma unroll
            for (int j = 0; j < 8; ++j) {
                int uu = j * 256 + tid, row = uu >> 3, u = uu & 7;
                cpa16(sb + FS_OFF + ((kc + 1) & 1) * FS_SZ
                          + (uint32_t)(row * 8 + (u ^ (row & 7))) * 16,
                      frow + (size_t)row * DIM + (kc + 1) * 64 + u * 8);
            }
            cp_commit();
            cp_wait<1>();
        } else {
            cp_wait<0>();
        }
        __syncthreads();

        const uint32_t fb = sb + FS_OFF + (kc & 1) * FS_SZ;
        const uint32_t wb = sb + kc * 16384;
        #pragma unroll
        for (int s = 0; s < 4; ++s) {              // 4 x k16 per chunk
            uint32_t a[2][4];
            #pragma unroll
            for (int mt = 0; mt < 2; ++mt) {
                int r0 = w * 32 + mt * 16 + g, r1 = r0 + 8;
                a[mt][0] = lds_u32(fb + (uint32_t)(r0 * 8 + ((2*s)   ^ (r0 & 7))) * 16 + 4 * t);
                a[mt][1] = lds_u32(fb + (uint32_t)(r1 * 8 + ((2*s)   ^ (r1 & 7))) * 16 + 4 * t);
                a[mt][2] = lds_u32(fb + (uint32_t)(r0 * 8 + ((2*s+1) ^ (r0 & 7))) * 16 + 4 * t);
                a[mt][3] = lds_u32(fb + (uint32_t)(r1 * 8 + ((2*s+1) ^ (r1 & 7))) * 16 + 4 * t);
            }
            #pragma unroll
            for (int nt = 0; nt < 16; ++nt) {
                int cn = nt * 8 + g;
                uint32_t b[2];
                b[0] = lds_u32(wb + (uint32_t)(cn * 8 + ((2*s)   ^ (cn & 7))) * 16 + 4 * t);
                b[1] = lds_u32(wb + (uint32_t)(cn * 8 + ((2*s+1) ^ (cn & 7))) * 16 + 4 * t);
                mma_bf16(acc[0][nt], a[0], b);
                mma_bf16(acc[1][nt], a[1], b);
            }
        }
        __syncthreads();
    }

    float Jtot = 0.f;
    #pragma unroll
    for (int mt = 0; mt < 2; ++mt) {
        #pragma unroll
        for (int h = 0; h < 2; ++h) {
            int j0 = h * 2;
            float mS = -1e30f, mT = -1e30f, mM = -1e30f;
            #pragma unroll
            for (int i = 0; i < 16; ++i) {
                int n = i >> 1, j = i & 1, c = n * 8 + 2 * t + j;
                float Sv = acc[mt][n][j0 + j], Tv = acc[mt][n + 8][j0 + j];
                mS = fmaxf(mS, Sv * inv_s[c]);
                mT = fmaxf(mT, Tv * inv_s[64 + c]);
                mM = fmaxf(mM, (Sv + Tv) * inv_s[128 + c]);
            }
            mS = qmax(mS); mT = qmax(mT); mM = qmax(mM);
            float zS = 0.f, zT = 0.f, zM = 0.f;
            #pragma unroll
            for (int i = 0; i < 16; ++i) {
                int n = i >> 1, j = i & 1, c = n * 8 + 2 * t + j;
                float Sv = acc[mt][n][j0 + j], Tv = acc[mt][n + 8][j0 + j];
                zS += __expf(Sv * inv_s[c] - mS);
                zT += __expf(Tv * inv_s[64 + c] - mT);
                zM += __expf((Sv + Tv) * inv_s[128 + c] - mM);
            }
            zS = qsum(zS); zT = qsum(zT); zM = qsum(zM);
            float lseS = mS + __logf(zS), lseT = mT + __logf(zT), lseM = mM + __logf(zM);
            float J = 0.f;
            #pragma unroll
            for (int i = 0; i < 16; ++i) {
                int n = i >> 1, j = i & 1, c = n * 8 + 2 * t + j;
                float Sv = acc[mt][n][j0 + j], Tv = acc[mt][n + 8][j0 + j];
                float ls = Sv * inv_s[c] - lseS;
                float lt = Tv * inv_s[64 + c] - lseT;
                float lm = (Sv + Tv) * inv_s[128 + c] - lseM;
                float es = __expf(ls), et = __expf(lt), em = __expf(lm);
                J += (et - es) * (lt - ls) + (em - es) * (lm - ls) + (em - et) * (lm - lt);
            }
            Jtot += qsum(J);
        }
    }
    Jtot += __shfl_xor_sync(~0u, Jtot, 4);
    Jtot += __shfl_xor_sync(~0u, Jtot, 8);
    Jtot += __shfl_xor_sync(~0u, Jtot, 16);
    if (lane == 0) red[w] = Jtot;
    __syncthreads();
    if (tid == 0) {
        float bs = 0.f;
        #pragma unroll
        for (int i = 0; i < 8; ++i) bs += red[i];
        atomicAdd(&g_acc, (double)bs);
    }
}

__global__ void k_final(float* out) {
    out[0] = (float)(g_acc * (0.5 / (3.0 * 131072.0 * 64.0)));
}

extern "C" void kernel_launch(void* const* d_in, const int* in_sizes, int n_in,
                              void* d_out, int out_size) {
    const float* src = (const float*)d_in[0];
    const float* trg = (const float*)d_in[1];
    const int*   sl  = (const int*)d_in[2];
    const int*   tl  = (const int*)d_in[3];

    cudaFuncSetAttribute(k_segsum, cudaFuncAttributeMaxDynamicSharedMemorySize, 65536);
    cudaFuncSetAttribute(k_main,   cudaFuncAttributeMaxDynamicSharedMemorySize, SMEM_MAIN);

    k_detect<<<1, 1>>>(sl);
    k_zero<<<1, 256>>>();
    k_segsum<<<512, 256, 65536>>>(src, trg, sl, tl);
    k_red<<<64, 512>>>();
    k_main<<<512, 256, SMEM_MAIN>>>();
    k_final<<<1, 1>>>((float*)d_out);
}

// round 5
// speedup vs baseline: 1.5282x; 1.1347x over previous
#include <cuda_runtime.h>
#include <cuda_bf16.h>
#include <cstdint>

#define NCLS 64
#define DIM 256
#define NROWS 65536
#define TOTROWS 131072

__device__ __align__(16) __nv_bfloat16 g_featbf[(size_t)TOTROWS * DIM];
__device__ float  g_scratch[2 * 128 * NCLS * 256];     // [feat][chunk][cls][k] 16MB
__device__ float  g_wsum4[4 * 32768];                  // quarter partial sums
__device__ int    g_icnt[2][NCLS];
__device__ __align__(16) __nv_bfloat16 g_wbf[4 * 8192];  // W bf16 pre-swizzled
__device__ float  g_inv[3 * NCLS];
__device__ double g_acc;
__device__ int    g_lstride;

__device__ __forceinline__ uint32_t smem_u32(const void* p) {
    uint32_t r;
    asm("{ .reg .u64 t; cvta.to.shared.u64 t, %1; cvt.u32.u64 %0, t; }" : "=r"(r) : "l"(p));
    return r;
}
__device__ __forceinline__ void cpa16(uint32_t dst, const void* src) {
    asm volatile("cp.async.cg.shared.global [%0], [%1], 16;" :: "r"(dst), "l"(src));
}
__device__ __forceinline__ void cp_commit() { asm volatile("cp.async.commit_group;"); }
template<int N> __device__ __forceinline__ void cp_wait() {
    asm volatile("cp.async.wait_group %0;" :: "n"(N));
}
__device__ __forceinline__ uint32_t lds_u32(uint32_t a) {
    uint32_t v; asm volatile("ld.shared.b32 %0, [%1];" : "=r"(v) : "r"(a)); return v;
}
__device__ __forceinline__ void mma_bf16(float* d, const uint32_t* a, const uint32_t* b) {
    asm volatile("mma.sync.aligned.m16n8k16.row.col.f32.bf16.bf16.f32 "
        "{%0,%1,%2,%3}, {%4,%5,%6,%7}, {%8,%9}, {%0,%1,%2,%3};"
        : "+f"(d[0]), "+f"(d[1]), "+f"(d[2]), "+f"(d[3])
        : "r"(a[0]), "r"(a[1]), "r"(a[2]), "r"(a[3]), "r"(b[0]), "r"(b[1]));
}
__device__ __forceinline__ float qmax(float v) {
    v = fmaxf(v, __shfl_xor_sync(~0u, v, 1));
    v = fmaxf(v, __shfl_xor_sync(~0u, v, 2));
    return v;
}
__device__ __forceinline__ float qsum(float v) {
    v += __shfl_xor_sync(~0u, v, 1);
    v += __shfl_xor_sync(~0u, v, 2);
    return v;
}

__global__ void k_detect(const int* __restrict__ lbl) {
    bool oz = true;
    #pragma unroll
    for (int i = 0; i < 64; ++i) oz &= (lbl[2 * i + 1] == 0);
    g_lstride = oz ? 2 : 1;
}

__global__ void k_zero() {
    int i = threadIdx.x;
    if (i < 128) ((int*)g_icnt)[i] = 0;
    if (i == 128) g_acc = 0.0;
}

// ---- label histogram: 64 blocks x 256 thr; block covers 2048 labels ----
__global__ void __launch_bounds__(256) k_hist(const int* __restrict__ sl,
                                              const int* __restrict__ tl) {
    __shared__ int h[NCLS];
    const int feat = blockIdx.x >> 5;
    const int* lp = feat ? tl : sl;
    const int ls = g_lstride, tid = threadIdx.x;
    if (tid < NCLS) h[tid] = 0;
    __syncthreads();
    const int base = (blockIdx.x & 31) * 2048;
    #pragma unroll
    for (int i = 0; i < 8; ++i)
        atomicAdd(&h[lp[(base + tid + i * 256) * ls] & 63], 1);
    __syncthreads();
    if (tid < NCLS) atomicAdd(&g_icnt[feat][tid], h[tid]);
}

// ---- segment sums: 512 blocks (2 feat x 2 colhalf x 128 chunks), 128 thr ----
// block: 512 rows x 128 cols; bins private per thread-column (32KB)
__global__ void __launch_bounds__(128) k_segsum(const float* __restrict__ src,
        const float* __restrict__ trg, const int* __restrict__ sl,
        const int* __restrict__ tl) {
    extern __shared__ float bins[];            // [64][128]
    __shared__ int lbl_s[512];
    const int feat = blockIdx.x >> 8, half = (blockIdx.x >> 7) & 1,
              chunk = blockIdx.x & 127;
    const float* fp = feat ? trg : src;
    const int*   lp = feat ? tl : sl;
    const int ls = g_lstride, tid = threadIdx.x;
    const int d = half * 128 + tid;
    const int base = chunk * 512;

    #pragma unroll
    for (int i = 0; i < 4; ++i)
        lbl_s[tid + i * 128] = lp[(base + tid + i * 128) * ls] & 63;
    #pragma unroll
    for (int c = 0; c < NCLS; ++c) bins[c * 128 + tid] = 0.f;
    __syncthreads();

    const float* fin = fp + (size_t)base * DIM + d;
    __nv_bfloat16* outb = g_featbf + (size_t)(feat * NROWS + base) * DIM + d;

    #pragma unroll 2
    for (int r0 = 0; r0 < 512; r0 += 8) {
        int cc[8]; float ff[8];
        #pragma unroll
        for (int i = 0; i < 8; ++i) cc[i] = lbl_s[r0 + i];
        #pragma unroll
        for (int i = 0; i < 8; ++i) ff[i] = fin[(size_t)(r0 + i) * DIM];
        #pragma unroll
        for (int i = 0; i < 8; ++i) outb[(size_t)(r0 + i) * DIM] = __float2bfloat16(ff[i]);
        #pragma unroll
        for (int i = 0; i < 8; ++i) bins[cc[i] * 128 + tid] += ff[i];
    }
    // no sync needed: each thread owns its column
    float* sc = g_scratch + ((size_t)(feat * 128 + chunk) * NCLS) * 256 + d;
    #pragma unroll 8
    for (int c = 0; c < NCLS; ++c) sc[c * 256] = bins[c * 128 + tid];
}

// ---- reduce stage 1: 256 blocks x 512 thr; 4 threads per output elem ----
__global__ void __launch_bounds__(512) k_red() {
    int q = blockIdx.x * 512 + threadIdx.x;    // 0..131071
    int quarter = q >> 15, elem = q & 32767;
    int cls = elem >> 8, k = elem & 255;
    int feat = cls >> 6, c = cls & 63;
    const float* p = g_scratch
        + ((size_t)(feat * 128 + quarter * 32) * NCLS + c) * 256 + k;
    float s = 0.f;
    #pragma unroll 8
    for (int ch = 0; ch < 32; ++ch) s += p[(size_t)ch * (NCLS * 256)];
    g_wsum4[quarter * 32768 + elem] = s;
}

// ---- reduce stage 2: combine quarters, swizzle to bf16 W, build inv ----
__global__ void __launch_bounds__(512) k_prep() {
    int idx = blockIdx.x * 512 + threadIdx.x;  // 0..32767
    float s = g_wsum4[idx] + g_wsum4[32768 + idx]
            + g_wsum4[65536 + idx] + g_wsum4[98304 + idx];
    int cls = idx >> 8, k = idx & 255;
    int kc = k >> 6, u = (k >> 3) & 7, e = k & 7;
    int phys = cls * 8 + (u ^ (cls & 7));
    g_wbf[kc * 8192 + phys * 8 + e] = __float2bfloat16(s);
    if (idx < 3 * NCLS) {
        int which = idx >> 6, c2 = idx & 63;
        float cs = (float)g_icnt[0][c2], ct = (float)g_icnt[1][c2];
        g_inv[idx] = (which == 0) ? 1.f / cs : (which == 1) ? 1.f / ct : 1.f / (cs + ct);
    }
}

// ---- fused bf16 GEMM + softmax/KL (unchanged core) ----
#define FS_OFF 65536
#define FS_SZ  32768
#define INV_OFF (FS_OFF + 2 * FS_SZ)
#define RED_OFF (INV_OFF + 768)
#define SMEM_MAIN (RED_OFF + 64)

__global__ void __launch_bounds__(256, 1) k_main() {
    extern __shared__ unsigned char sm[];
    float* inv_s = (float*)(sm + INV_OFF);
    float* red   = (float*)(sm + RED_OFF);
    const uint32_t sb = smem_u32(sm);
    const int tid = threadIdx.x, w = tid >> 5, lane = tid & 31;
    const int g = lane >> 2, t = lane & 3;

    #pragma unroll
    for (int j = 0; j < 16; ++j) {
        int uu = j * 256 + tid;
        cpa16(sb + uu * 16, g_wbf + uu * 8);
    }
    if (tid < 192) inv_s[tid] = g_inv[tid];

    const __nv_bfloat16* frow = g_featbf + (size_t)blockIdx.x * 256 * DIM;
    #pragma unroll
    for (int j = 0; j < 8; ++j) {
        int uu = j * 256 + tid, row = uu >> 3, u = uu & 7;
        cpa16(sb + FS_OFF + (uint32_t)(row * 8 + (u ^ (row & 7))) * 16,
              frow + (size_t)row * DIM + u * 8);
    }
    cp_commit();

    float acc[2][16][4];
    #pragma unroll
    for (int x = 0; x < 2; ++x)
        #pragma unroll
        for (int y = 0; y < 16; ++y)
            #pragma unroll
            for (int z = 0; z < 4; ++z) acc[x][y][z] = 0.f;

    #pragma unroll
    for (int kc = 0; kc < 4; ++kc) {
        if (kc < 3) {
            #pragma unroll
            for (int j = 0; j < 8; ++j) {
                int uu = j * 256 + tid, row = uu >> 3, u = uu & 7;
                cpa16(sb + FS_OFF + ((kc + 1) & 1) * FS_SZ
                          + (uint32_t)(row * 8 + (u ^ (row & 7))) * 16,
                      frow + (size_t)row * DIM + (kc + 1) * 64 + u * 8);
            }
            cp_commit();
            cp_wait<1>();
        } else {
            cp_wait<0>();
        }
        __syncthreads();

        const uint32_t fb = sb + FS_OFF + (kc & 1) * FS_SZ;
        const uint32_t wb = sb + kc * 16384;
        #pragma unroll
        for (int s = 0; s < 4; ++s) {
            uint32_t a[2][4];
            #pragma unroll
            for (int mt = 0; mt < 2; ++mt) {
                int r0 = w * 32 + mt * 16 + g, r1 = r0 + 8;
                a[mt][0] = lds_u32(fb + (uint32_t)(r0 * 8 + ((2*s)   ^ (r0 & 7))) * 16 + 4 * t);
                a[mt][1] = lds_u32(fb + (uint32_t)(r1 * 8 + ((2*s)   ^ (r1 & 7))) * 16 + 4 * t);
                a[mt][2] = lds_u32(fb + (uint32_t)(r0 * 8 + ((2*s+1) ^ (r0 & 7))) * 16 + 4 * t);
                a[mt][3] = lds_u32(fb + (uint32_t)(r1 * 8 + ((2*s+1) ^ (r1 & 7))) * 16 + 4 * t);
            }
            #pragma unroll
            for (int nt = 0; nt < 16; ++nt) {
                int cn = nt * 8 + g;
                uint32_t b[2];
                b[0] = lds_u32(wb + (uint32_t)(cn * 8 + ((2*s)   ^ (cn & 7))) * 16 + 4 * t);
                b[1] = lds_u32(wb + (uint32_t)(cn * 8 + ((2*s+1) ^ (cn & 7))) * 16 + 4 * t);
                mma_bf16(acc[0][nt], a[0], b);
                mma_bf16(acc[1][nt], a[1], b);
            }
        }
        __syncthreads();
    }

    float Jtot = 0.f;
    #pragma unroll
    for (int mt = 0; mt < 2; ++mt) {
        #pragma unroll
        for (int h = 0; h < 2; ++h) {
            int j0 = h * 2;
            float mS = -1e30f, mT = -1e30f, mM = -1e30f;
            #pragma unroll
            for (int i = 0; i < 16; ++i) {
                int n = i >> 1, j = i & 1, c = n * 8 + 2 * t + j;
                float Sv = acc[mt][n][j0 + j], Tv = acc[mt][n + 8][j0 + j];
                mS = fmaxf(mS, Sv * inv_s[c]);
                mT = fmaxf(mT, Tv * inv_s[64 + c]);
                mM = fmaxf(mM, (Sv + Tv) * inv_s[128 + c]);
            }
            mS = qmax(mS); mT = qmax(mT); mM = qmax(mM);
            float zS = 0.f, zT = 0.f, zM = 0.f;
            #pragma unroll
            for (int i = 0; i < 16; ++i) {
                int n = i >> 1, j = i & 1, c = n * 8 + 2 * t + j;
                float Sv = acc[mt][n][j0 + j], Tv = acc[mt][n + 8][j0 + j];
                zS += __expf(Sv * inv_s[c] - mS);
                zT += __expf(Tv * inv_s[64 + c] - mT);
                zM += __expf((Sv + Tv) * inv_s[128 + c] - mM);
            }
            zS = qsum(zS); zT = qsum(zT); zM = qsum(zM);
            float lseS = mS + __logf(zS), lseT = mT + __logf(zT), lseM = mM + __logf(zM);
            float J = 0.f;
            #pragma unroll
            for (int i = 0; i < 16; ++i) {
                int n = i >> 1, j = i & 1, c = n * 8 + 2 * t + j;
                float Sv = acc[mt][n][j0 + j], Tv = acc[mt][n + 8][j0 + j];
                float ls = Sv * inv_s[c] - lseS;
                float lt = Tv * inv_s[64 + c] - lseT;
                float lm = (Sv + Tv) * inv_s[128 + c] - lseM;
                float es = __expf(ls), et = __expf(lt), em = __expf(lm);
                J += (et - es) * (lt - ls) + (em - es) * (lm - ls) + (em - et) * (lm - lt);
            }
            Jtot += qsum(J);
        }
    }
    Jtot += __shfl_xor_sync(~0u, Jtot, 4);
    Jtot += __shfl_xor_sync(~0u, Jtot, 8);
    Jtot += __shfl_xor_sync(~0u, Jtot, 16);
    if (lane == 0) red[w] = Jtot;
    __syncthreads();
    if (tid == 0) {
        float bs = 0.f;
        #pragma unroll
        for (int i = 0; i < 8; ++i) bs += red[i];
        atomicAdd(&g_acc, (double)bs);
    }
}

__global__ void k_final(float* out) {
    out[0] = (float)(g_acc * (0.5 / (3.0 * 131072.0 * 64.0)));
}

extern "C" void kernel_launch(void* const* d_in, const int* in_sizes, int n_in,
                              void* d_out, int out_size) {
    const float* src = (const float*)d_in[0];
    const float* trg = (const float*)d_in[1];
    const int*   sl  = (const int*)d_in[2];
    const int*   tl  = (const int*)d_in[3];

    cudaFuncSetAttribute(k_segsum, cudaFuncAttributeMaxDynamicSharedMemorySize, 32768);
    cudaFuncSetAttribute(k_main,   cudaFuncAttributeMaxDynamicSharedMemorySize, SMEM_MAIN);

    k_detect<<<1, 1>>>(sl);
    k_zero<<<1, 256>>>();
    k_hist<<<64, 256>>>(sl, tl);
    k_segsum<<<512, 128, 32768>>>(src, trg, sl, tl);
    k_red<<<256, 512>>>();
    k_prep<<<64, 512>>>();
    k_main<<<512, 256, SMEM_MAIN>>>();
    k_final<<<1, 1>>>((float*)d_out);
}